// round 1
// baseline (speedup 1.0000x reference)
#include <cuda_runtime.h>

// Problem constants (fixed by reference: B=8, H=512, W=512)
#define BB 8
#define HH 512
#define WW 512
constexpr int HW   = HH * WW;        // 262144
constexpr int NPIX = BB * HW;        // 2097152

__device__ double g_accum;

__global__ void zero_accum_k() { g_accum = 0.0; }

__global__ void __launch_bounds__(256) flow_loss_k(
    const float* __restrict__ roi,
    const float* __restrict__ hm0,  const float* __restrict__ hm1,  const float* __restrict__ hm2,
    const float* __restrict__ r1pf, const float* __restrict__ r1pb,
    const float* __restrict__ r1nf, const float* __restrict__ r1nb,
    const float* __restrict__ r0f,  const float* __restrict__ r0b,
    const float* __restrict__ r2f,  const float* __restrict__ r2b,
    const float* __restrict__ fA1,  const float* __restrict__ fB1,   // flow_0_1f, flow_1_0b
    const float* __restrict__ fA2,  const float* __restrict__ fB2)   // flow_1_2f, flow_2_1b
{
    float acc = 0.0f;
    const int stride = gridDim.x * blockDim.x;
    for (int p = blockIdx.x * blockDim.x + threadIdx.x; p < NPIX; p += stride) {
        const int x = p & (WW - 1);
        const int y = (p >> 9) & (HH - 1);
        const int b = p >> 18;

        const float r  = roi[p];
        const float h0 = hm0[p], h1 = hm1[p], h2 = hm2[p];
        const float pre  = fabsf(h0 - h1);
        const float post = fabsf(h1 - h2);

        float d;
        d = r1pf[p] - h1; float s1p = d * d;
        d = r1pb[p] - h1; s1p += d * d;
        d = r1nf[p] - h1; float s1n = d * d;
        d = r1nb[p] - h1; s1n += d * d;
        d = r0f[p]  - h0; float s0  = d * d;
        d = r0b[p]  - h0; s0  += d * d;
        d = r2f[p]  - h2; float s2  = d * d;
        d = r2b[p]  - h2; s2  += d * d;

        const float wp = r * (1.0f + pre);
        const float wn = r * (1.0f + post);
        acc += wp * (0.25f * s1p + 0.5f * s0) + wn * (0.25f * s1n + 0.5f * s2);

        // flow consistency: both pairs, 9 channels; shared roi weight
        const int fbase = b * (9 * HW) + (p - b * HW);   // index of channel 0 at (y,x)
        float facc = 0.0f;
        #pragma unroll
        for (int i = 0; i < 9; i++) {
            const int dy = (i < 3) ? 1 : ((i < 6) ? 0 : -1);
            const int m  = i % 3;
            const int dx = (m == 0) ? 1 : ((m == 1) ? 0 : -1);

            bool ok = true;
            if (dy ==  1) ok = ok && (y >= 1);
            if (dy == -1) ok = ok && (y <= HH - 2);
            if (dx ==  1) ok = ok && (x >= 1);
            if (dx == -1) ok = ok && (x <= WW - 2);

            if (ok) {
                const int aoff = fbase + i * HW;
                const int goff = fbase + (8 - i) * HW - dy * WW - dx;
                float a1 = fA1[aoff], g1 = fB1[goff];
                float a2 = fA2[aoff], g2 = fB2[goff];
                // clip to [EPS, 1-EPS]  (1-EPS rounds to 1.0f in fp32)
                a1 = fminf(fmaxf(a1, 1e-10f), 1.0f);
                g1 = fminf(fmaxf(g1, 1e-10f), 1.0f);
                a2 = fminf(fmaxf(a2, 1e-10f), 1.0f);
                g2 = fminf(fmaxf(g2, 1e-10f), 1.0f);
                const float d1 = a1 - g1;
                const float d2 = a2 - g2;
                facc += d1 * d1 + d2 * d2;
            }
        }
        acc += facc * r * (1.0f / 9.0f);
    }

    // ---- block reduction: warp shuffle -> shared -> warp 0 -> atomicAdd(double) ----
    __shared__ float sdata[8];
    #pragma unroll
    for (int off = 16; off; off >>= 1)
        acc += __shfl_down_sync(0xffffffffu, acc, off);
    const int lane = threadIdx.x & 31;
    const int wid  = threadIdx.x >> 5;
    if (lane == 0) sdata[wid] = acc;
    __syncthreads();
    if (wid == 0) {
        float v = (lane < 8) ? sdata[lane] : 0.0f;
        #pragma unroll
        for (int off = 4; off; off >>= 1)
            v += __shfl_down_sync(0xffffffffu, v, off);
        if (lane == 0) atomicAdd(&g_accum, (double)v);
    }
}

__global__ void writeback_k(float* out) { out[0] = (float)g_accum; }

extern "C" void kernel_launch(void* const* d_in, const int* in_sizes, int n_in,
                              void* d_out, int out_size) {
    const float* roi  = (const float*)d_in[0];
    // d_in[1] = boundary_mask : unused by the reference loss
    const float* hm0  = (const float*)d_in[2];
    const float* hm1  = (const float*)d_in[3];
    const float* hm2  = (const float*)d_in[4];
    const float* r1pf = (const float*)d_in[5];
    const float* r1pb = (const float*)d_in[6];
    const float* r1nf = (const float*)d_in[7];
    const float* r1nb = (const float*)d_in[8];
    const float* r0f  = (const float*)d_in[9];
    const float* r0b  = (const float*)d_in[10];
    const float* r2f  = (const float*)d_in[11];
    const float* r2b  = (const float*)d_in[12];
    const float* fA1  = (const float*)d_in[13];
    const float* fB1  = (const float*)d_in[14];
    const float* fA2  = (const float*)d_in[15];
    const float* fB2  = (const float*)d_in[16];

    zero_accum_k<<<1, 1>>>();
    // 2048 blocks x 256 threads -> each thread handles 4 pixels (grid-stride)
    flow_loss_k<<<2048, 256>>>(roi, hm0, hm1, hm2,
                               r1pf, r1pb, r1nf, r1nb,
                               r0f, r0b, r2f, r2b,
                               fA1, fB1, fA2, fB2);
    writeback_k<<<1, 1>>>((float*)d_out);
}

// round 2
// speedup vs baseline: 1.0232x; 1.0232x over previous
#include <cuda_runtime.h>

// Problem constants (fixed by reference: B=8, H=512, W=512)
#define BB 8
#define HH 512
#define WW 512
constexpr int HW   = HH * WW;        // 262144
constexpr int NPIX = BB * HW;        // 2097152
constexpr int GRID = 2048;
constexpr int TPB  = 256;

__device__ double       g_accum = 0.0;
__device__ unsigned int g_done  = 0;

__global__ void __launch_bounds__(TPB) flow_loss_k(
    const float* __restrict__ roi,
    const float* __restrict__ hm0,  const float* __restrict__ hm1,  const float* __restrict__ hm2,
    const float* __restrict__ r1pf, const float* __restrict__ r1pb,
    const float* __restrict__ r1nf, const float* __restrict__ r1nb,
    const float* __restrict__ r0f,  const float* __restrict__ r0b,
    const float* __restrict__ r2f,  const float* __restrict__ r2b,
    const float* __restrict__ fA1,  const float* __restrict__ fB1,   // flow_0_1f, flow_1_0b
    const float* __restrict__ fA2,  const float* __restrict__ fB2,   // flow_1_2f, flow_2_1b
    float* __restrict__ out)
{
    float acc = 0.0f;
    const int stride = gridDim.x * blockDim.x;
    for (int p = blockIdx.x * blockDim.x + threadIdx.x; p < NPIX; p += stride) {
        const int x = p & (WW - 1);
        const int y = (p >> 9) & (HH - 1);
        const int b = p >> 18;

        const float r  = roi[p];
        const float h0 = hm0[p], h1 = hm1[p], h2 = hm2[p];
        const float pre  = fabsf(h0 - h1);
        const float post = fabsf(h1 - h2);

        float d;
        d = r1pf[p] - h1; float s1p = d * d;
        d = r1pb[p] - h1; s1p += d * d;
        d = r1nf[p] - h1; float s1n = d * d;
        d = r1nb[p] - h1; s1n += d * d;
        d = r0f[p]  - h0; float s0  = d * d;
        d = r0b[p]  - h0; s0  += d * d;
        d = r2f[p]  - h2; float s2  = d * d;
        d = r2b[p]  - h2; s2  += d * d;

        const float wp = r * (1.0f + pre);
        const float wn = r * (1.0f + post);
        acc += wp * (0.25f * s1p + 0.5f * s0) + wn * (0.25f * s1n + 0.5f * s2);

        // flow consistency: both pairs, 9 channels; shared roi weight
        const int fbase = b * (9 * HW) + (p - b * HW);   // index of channel 0 at (y,x)
        float facc = 0.0f;
        #pragma unroll
        for (int i = 0; i < 9; i++) {
            const int dy = (i < 3) ? 1 : ((i < 6) ? 0 : -1);
            const int m  = i % 3;
            const int dx = (m == 0) ? 1 : ((m == 1) ? 0 : -1);

            bool ok = true;
            if (dy ==  1) ok = ok && (y >= 1);
            if (dy == -1) ok = ok && (y <= HH - 2);
            if (dx ==  1) ok = ok && (x >= 1);
            if (dx == -1) ok = ok && (x <= WW - 2);

            if (ok) {
                const int aoff = fbase + i * HW;
                const int goff = fbase + (8 - i) * HW - dy * WW - dx;
                float a1 = fA1[aoff], g1 = fB1[goff];
                float a2 = fA2[aoff], g2 = fB2[goff];
                // clip to [EPS, 1-EPS]  (1-EPS rounds to 1.0f in fp32)
                a1 = fminf(fmaxf(a1, 1e-10f), 1.0f);
                g1 = fminf(fmaxf(g1, 1e-10f), 1.0f);
                a2 = fminf(fmaxf(a2, 1e-10f), 1.0f);
                g2 = fminf(fmaxf(g2, 1e-10f), 1.0f);
                const float d1 = a1 - g1;
                const float d2 = a2 - g2;
                facc += d1 * d1 + d2 * d2;
            }
        }
        acc += facc * r * (1.0f / 9.0f);
    }

    // ---- block reduction: warp shuffle -> shared -> warp 0 -> atomicAdd(double) ----
    __shared__ float sdata[TPB / 32];
    #pragma unroll
    for (int off = 16; off; off >>= 1)
        acc += __shfl_down_sync(0xffffffffu, acc, off);
    const int lane = threadIdx.x & 31;
    const int wid  = threadIdx.x >> 5;
    if (lane == 0) sdata[wid] = acc;
    __syncthreads();

    if (wid == 0) {
        float v = (lane < TPB / 32) ? sdata[lane] : 0.0f;
        #pragma unroll
        for (int off = 4; off; off >>= 1)
            v += __shfl_down_sync(0xffffffffu, v, off);

        if (lane == 0) {
            atomicAdd(&g_accum, (double)v);
            __threadfence();
            const unsigned int ticket = atomicAdd(&g_done, 1u);
            if (ticket == gridDim.x - 1) {
                // last block: all partials visible (threadfence + atomic order)
                out[0] = (float)g_accum;
                // reset state so the next graph replay starts clean
                g_accum = 0.0;
                __threadfence();
                g_done = 0;
            }
        }
    }
}

extern "C" void kernel_launch(void* const* d_in, const int* in_sizes, int n_in,
                              void* d_out, int out_size) {
    const float* roi  = (const float*)d_in[0];
    // d_in[1] = boundary_mask : unused by the reference loss
    const float* hm0  = (const float*)d_in[2];
    const float* hm1  = (const float*)d_in[3];
    const float* hm2  = (const float*)d_in[4];
    const float* r1pf = (const float*)d_in[5];
    const float* r1pb = (const float*)d_in[6];
    const float* r1nf = (const float*)d_in[7];
    const float* r1nb = (const float*)d_in[8];
    const float* r0f  = (const float*)d_in[9];
    const float* r0b  = (const float*)d_in[10];
    const float* r2f  = (const float*)d_in[11];
    const float* r2b  = (const float*)d_in[12];
    const float* fA1  = (const float*)d_in[13];
    const float* fB1  = (const float*)d_in[14];
    const float* fA2  = (const float*)d_in[15];
    const float* fB2  = (const float*)d_in[16];

    flow_loss_k<<<GRID, TPB>>>(roi, hm0, hm1, hm2,
                               r1pf, r1pb, r1nf, r1nb,
                               r0f, r0b, r2f, r2b,
                               fA1, fB1, fA2, fB2,
                               (float*)d_out);
}

// round 3
// speedup vs baseline: 1.1550x; 1.1288x over previous
#include <cuda_runtime.h>

// Problem constants (fixed by reference: B=8, H=512, W=512)
#define HH 512
#define WW 512
constexpr int HW   = HH * WW;        // 262144
constexpr int NPIX = 8 * HW;         // 2097152
constexpr int TPB  = 256;
constexpr int GRID = NPIX / 4 / TPB; // 2048  (exact, no remainder)

__device__ double       g_accum = 0.0;
__device__ unsigned int g_done  = 0;

__device__ __forceinline__ float4 ld4(const float* p) {
    return __ldg(reinterpret_cast<const float4*>(p));
}
__device__ __forceinline__ float clipf(float v) {
    return fminf(fmaxf(v, 1e-10f), 1.0f);
}

__global__ void __launch_bounds__(TPB) flow_loss_k(
    const float* __restrict__ roi,
    const float* __restrict__ hm0,  const float* __restrict__ hm1,  const float* __restrict__ hm2,
    const float* __restrict__ r1pf, const float* __restrict__ r1pb,
    const float* __restrict__ r1nf, const float* __restrict__ r1nb,
    const float* __restrict__ r0f,  const float* __restrict__ r0b,
    const float* __restrict__ r2f,  const float* __restrict__ r2b,
    const float* __restrict__ fA1,  const float* __restrict__ fB1,   // flow_0_1f, flow_1_0b
    const float* __restrict__ fA2,  const float* __restrict__ fB2,   // flow_1_2f, flow_2_1b
    float* __restrict__ out)
{
    const int v  = blockIdx.x * TPB + threadIdx.x;  // vector id (4 pixels)
    const int p  = v << 2;
    const int x4 = p & (WW - 1);            // 0,4,...,508
    const int y  = (p >> 9) & (HH - 1);
    const int bb = p >> 18;

    // ---- aligned streams: 12 x LDG.128 ----
    const float4 r4  = ld4(roi  + p);
    const float4 h04 = ld4(hm0  + p);
    const float4 h14 = ld4(hm1  + p);
    const float4 h24 = ld4(hm2  + p);
    const float4 a1p = ld4(r1pf + p);
    const float4 b1p = ld4(r1pb + p);
    const float4 a1n = ld4(r1nf + p);
    const float4 b1n = ld4(r1nb + p);
    const float4 a0  = ld4(r0f  + p);
    const float4 b0  = ld4(r0b  + p);
    const float4 a2  = ld4(r2f  + p);
    const float4 b2  = ld4(r2b  + p);

    const float* R  = (const float*)&r4;
    const float* H0 = (const float*)&h04;
    const float* H1 = (const float*)&h14;
    const float* H2 = (const float*)&h24;
    const float* P1F = (const float*)&a1p; const float* P1B = (const float*)&b1p;
    const float* N1F = (const float*)&a1n; const float* N1B = (const float*)&b1n;
    const float* F0  = (const float*)&a0;  const float* B0  = (const float*)&b0;
    const float* F2  = (const float*)&a2;  const float* B2  = (const float*)&b2;

    float acc = 0.0f;
    #pragma unroll
    for (int j = 0; j < 4; j++) {
        const float r  = R[j];
        const float h0 = H0[j], h1 = H1[j], h2 = H2[j];
        const float pre  = fabsf(h0 - h1);
        const float post = fabsf(h1 - h2);

        float d;
        d = P1F[j] - h1; float s1p = d * d;
        d = P1B[j] - h1; s1p += d * d;
        d = N1F[j] - h1; float s1n = d * d;
        d = N1B[j] - h1; s1n += d * d;
        d = F0[j]  - h0; float s0  = d * d;
        d = B0[j]  - h0; s0  += d * d;
        d = F2[j]  - h2; float s2  = d * d;
        d = B2[j]  - h2; s2  += d * d;

        acc += r * (1.0f + pre)  * (0.25f * s1p + 0.5f * s0)
             + r * (1.0f + post) * (0.25f * s1n + 0.5f * s2);
    }

    // ---- flow consistency (both pairs share index math) ----
    float facc[4] = {0.f, 0.f, 0.f, 0.f};
    const int c0 = bb * (9 * HW) + y * WW + x4;   // channel 0 at (y, x4)
    const bool edgeL = (x4 == 0);                 // lane 0 invalid for dx=+1
    const bool edgeR = (x4 == WW - 4);            // lane 3 invalid for dx=-1

    #pragma unroll
    for (int i = 0; i < 9; i++) {
        const int dy = (i < 3) ? 1 : ((i < 6) ? 0 : -1);
        const int m  = i % 3;
        const int dx = (m == 0) ? 1 : ((m == 1) ? 0 : -1);

        const bool vrow = (dy == 1) ? (y >= 1) : ((dy == -1) ? (y <= HH - 2) : true);
        if (!vrow) continue;

        const int ao = c0 + i * HW;
        const int go = c0 + (8 - i) * HW - dy * WW;   // aligned base (dx handled by lane shift)

        const float4 av1 = ld4(fA1 + ao);
        const float4 av2 = ld4(fA2 + ao);
        const float4 bv1 = ld4(fB1 + go);
        const float4 bv2 = ld4(fB2 + go);
        const float* A1 = (const float*)&av1; const float* A2 = (const float*)&av2;
        const float* Bv1 = (const float*)&bv1; const float* Bv2 = (const float*)&bv2;

        if (dx == 0) {
            #pragma unroll
            for (int j = 0; j < 4; j++) {
                const float d1 = clipf(A1[j]) - clipf(Bv1[j]);
                const float d2 = clipf(A2[j]) - clipf(Bv2[j]);
                facc[j] += d1 * d1 + d2 * d2;
            }
        } else if (dx == 1) {
            // lane j needs b at x4+j-1; lane 0 straddles (scalar), invalid at x4==0
            float s1 = 0.f, s2 = 0.f;
            if (!edgeL) { s1 = __ldg(fB1 + go - 1); s2 = __ldg(fB2 + go - 1); }
            if (!edgeL) {
                const float d1 = clipf(A1[0]) - clipf(s1);
                const float d2 = clipf(A2[0]) - clipf(s2);
                facc[0] += d1 * d1 + d2 * d2;
            }
            #pragma unroll
            for (int j = 1; j < 4; j++) {
                const float d1 = clipf(A1[j]) - clipf(Bv1[j - 1]);
                const float d2 = clipf(A2[j]) - clipf(Bv2[j - 1]);
                facc[j] += d1 * d1 + d2 * d2;
            }
        } else {  // dx == -1
            // lane j needs b at x4+j+1; lane 3 straddles (scalar), invalid at x4==508
            float s1 = 0.f, s2 = 0.f;
            if (!edgeR) { s1 = __ldg(fB1 + go + 4); s2 = __ldg(fB2 + go + 4); }
            #pragma unroll
            for (int j = 0; j < 3; j++) {
                const float d1 = clipf(A1[j]) - clipf(Bv1[j + 1]);
                const float d2 = clipf(A2[j]) - clipf(Bv2[j + 1]);
                facc[j] += d1 * d1 + d2 * d2;
            }
            if (!edgeR) {
                const float d1 = clipf(A1[3]) - clipf(s1);
                const float d2 = clipf(A2[3]) - clipf(s2);
                facc[3] += d1 * d1 + d2 * d2;
            }
        }
    }
    #pragma unroll
    for (int j = 0; j < 4; j++) acc += facc[j] * R[j] * (1.0f / 9.0f);

    // ---- block reduction: warp shuffle -> shared -> warp 0 -> atomicAdd(double) ----
    __shared__ float sdata[TPB / 32];
    #pragma unroll
    for (int off = 16; off; off >>= 1)
        acc += __shfl_down_sync(0xffffffffu, acc, off);
    const int lane = threadIdx.x & 31;
    const int wid  = threadIdx.x >> 5;
    if (lane == 0) sdata[wid] = acc;
    __syncthreads();

    if (wid == 0) {
        float t = (lane < TPB / 32) ? sdata[lane] : 0.0f;
        #pragma unroll
        for (int off = 4; off; off >>= 1)
            t += __shfl_down_sync(0xffffffffu, t, off);

        if (lane == 0) {
            atomicAdd(&g_accum, (double)t);
            __threadfence();
            const unsigned int ticket = atomicAdd(&g_done, 1u);
            if (ticket == gridDim.x - 1) {
                out[0] = (float)g_accum;
                g_accum = 0.0;          // reset for next graph replay
                __threadfence();
                g_done = 0;
            }
        }
    }
}

extern "C" void kernel_launch(void* const* d_in, const int* in_sizes, int n_in,
                              void* d_out, int out_size) {
    const float* roi  = (const float*)d_in[0];
    // d_in[1] = boundary_mask : unused by the reference loss
    const float* hm0  = (const float*)d_in[2];
    const float* hm1  = (const float*)d_in[3];
    const float* hm2  = (const float*)d_in[4];
    const float* r1pf = (const float*)d_in[5];
    const float* r1pb = (const float*)d_in[6];
    const float* r1nf = (const float*)d_in[7];
    const float* r1nb = (const float*)d_in[8];
    const float* r0f  = (const float*)d_in[9];
    const float* r0b  = (const float*)d_in[10];
    const float* r2f  = (const float*)d_in[11];
    const float* r2b  = (const float*)d_in[12];
    const float* fA1  = (const float*)d_in[13];
    const float* fB1  = (const float*)d_in[14];
    const float* fA2  = (const float*)d_in[15];
    const float* fB2  = (const float*)d_in[16];

    flow_loss_k<<<GRID, TPB>>>(roi, hm0, hm1, hm2,
                               r1pf, r1pb, r1nf, r1nb,
                               r0f, r0b, r2f, r2b,
                               fA1, fB1, fA2, fB2,
                               (float*)d_out);
}